// round 1
// baseline (speedup 1.0000x reference)
#include <cuda_runtime.h>
#include <cstdint>
#include <cstddef>

#define NB 128
#define NS 512
#define ND 128
#define NH 1024
#define NO 64
#define NIN 257
#define KP 264      // padded input size (multiple of 8)
#define NG 4096     // 4*H

// ---------------- device scratch (static; no allocations) ----------------
__device__ __align__(16) float d_xt[NS * NB * KP];        // rna(tf32) gathered inputs, ~69 MB
__device__ __align__(16) float d_wih[NG * KP];            // rna W_ih padded
__device__ __align__(16) float d_whh[NG * NH];            // rna W_hh
__device__ __align__(16) float d_bias[NG];                // b_ih + b_hh
__device__ __align__(16) float d_xg[(size_t)NS * NB * NG];// 1 GiB: precomputed input gates
__device__ __align__(16) float d_h[2][NB * NH];           // double-buffered hidden state (tf32-rna values)
__device__ unsigned long long g_cnt;                      // grid barrier counter

// ---------------- helpers ----------------
__device__ __forceinline__ unsigned smem_u32(const void* p) {
    return (unsigned)__cvta_generic_to_shared(p);
}
__device__ __forceinline__ void cpa16(unsigned s, const void* g) {
    asm volatile("cp.async.cg.shared.global [%0], [%1], 16;\n" :: "r"(s), "l"(g));
}
__device__ __forceinline__ void cp_commit() { asm volatile("cp.async.commit_group;\n"); }
__device__ __forceinline__ void cp_wait0() { asm volatile("cp.async.wait_group 0;\n" ::: "memory"); }
__device__ __forceinline__ void cp_wait1() { asm volatile("cp.async.wait_group 1;\n" ::: "memory"); }

__device__ __forceinline__ float to_tf32(float x) {
    asm("cvt.rna.tf32.f32 %0, %0;" : "+f"(x));
    return x;
}

__device__ __forceinline__ void mma8(float* c, const unsigned* a, const unsigned* b) {
    asm volatile(
        "mma.sync.aligned.m16n8k8.row.col.f32.tf32.tf32.f32 "
        "{%0,%1,%2,%3}, {%4,%5,%6,%7}, {%8,%9}, {%0,%1,%2,%3};\n"
        : "+f"(c[0]), "+f"(c[1]), "+f"(c[2]), "+f"(c[3])
        : "r"(a[0]), "r"(a[1]), "r"(a[2]), "r"(a[3]), "r"(b[0]), "r"(b[1]));
}

__device__ __forceinline__ float sigf(float x) { return 1.f / (1.f + __expf(-x)); }
__device__ __forceinline__ float tanhf_(float x) {
    float e = __expf(-2.f * fabsf(x));
    float t = (1.f - e) / (1.f + e);
    return copysignf(t, x);
}

// Grid barrier: monotonic counter (reset to 0 by prep kernel each launch).
__device__ __forceinline__ void gbar(unsigned long long target) {
    __threadfence();
    __syncthreads();
    if (threadIdx.x == 0) {
        atomicAdd(&g_cnt, 1ULL);
        while (*((volatile unsigned long long*)&g_cnt) < target) {}
        __threadfence();
    }
    __syncthreads();
}

// ---------------- prep kernels ----------------
__global__ void k_prep_xt(const float* __restrict__ x, const float* __restrict__ mask,
                          const float* __restrict__ ti) {
    int idx = blockIdx.x * 256 + threadIdx.x;
    if (idx >= NS * NB * KP) return;
    int r = idx / KP, k = idx - r * KP;
    int s = r >> 7, b = r & 127;
    float v = 0.f;
    if (k < ND)            v = x[(b * NS + s) * ND + k];
    else if (k < 2 * ND)   v = mask[(b * NS + s) * ND + (k - ND)];
    else if (k == 2 * ND)  v = ti[b * NS + s];
    d_xt[idx] = to_tf32(v);
}

__global__ void k_prep_w(const float* __restrict__ wih, const float* __restrict__ whh,
                         const float* __restrict__ bih, const float* __restrict__ bhh) {
    int idx = blockIdx.x * 256 + threadIdx.x;
    if (idx < NG * KP) {
        int g = idx / KP, k = idx - g * KP;
        float v = (k < NIN) ? wih[g * NIN + k] : 0.f;
        d_wih[idx] = to_tf32(v);
    }
    if (idx < NG * NH) d_whh[idx] = to_tf32(whh[idx]);
    if (idx < NG) d_bias[idx] = bih[idx] + bhh[idx];
    if (idx == 0) g_cnt = 0ULL;
}

// ---------------- XG GEMM: xg[s*128+b, g] = xt row · W_ih row + bias ----------------
// CTA tile: 128(M=batch, s fixed) x 64(N). K=264 in 11 stages of 24.
#define XA_STRIDE 28
#define XW_STRIDE 268
#define XG_SMEM (64 * XW_STRIDE * 4 + 2 * 128 * XA_STRIDE * 4)

__global__ void __launch_bounds__(256, 2) k_xg() {
    extern __shared__ float sm[];
    float* Wsm = sm;                       // [64][268]
    float* Asm = sm + 64 * XW_STRIDE;      // [2][128][28]
    const int tid = threadIdx.x;
    const int bx = blockIdx.x;             // n-tile 0..63
    const int s = blockIdx.y;              // 0..511
    const int n0 = bx * 64;
    const int row0 = s * NB;

    unsigned wbase = smem_u32(Wsm);
    unsigned abase = smem_u32(Asm);

    // W tile: 64 rows x 264 floats (66 x 16B chunks per row)
    for (int q = tid; q < 64 * 66; q += 256) {
        int r = q / 66, c = q - r * 66;
        cpa16(wbase + (unsigned)(r * XW_STRIDE + c * 4) * 4, d_wih + (n0 + r) * KP + c * 4);
    }
    // A stage 0: 128 rows x 24 floats (6 chunks/row)
    for (int q = tid; q < 128 * 6; q += 256) {
        int r = q / 6, c = q - r * 6;
        cpa16(abase + (unsigned)(r * XA_STRIDE + c * 4) * 4, d_xt + (row0 + r) * KP + c * 4);
    }
    cp_commit();

    const int wid = tid >> 5, l = tid & 31;
    const int wm = wid >> 1, wn = wid & 1;  // 4 x 2 warps, warp tile 32x32
    const int lr = l >> 2, lc = l & 3;

    float acc[2][4][4];
#pragma unroll
    for (int i = 0; i < 2; i++)
#pragma unroll
        for (int j = 0; j < 4; j++)
#pragma unroll
            for (int k = 0; k < 4; k++) acc[i][j][k] = 0.f;

    for (int st = 0; st < 11; st++) {
        float* Ab = Asm + (st & 1) * 128 * XA_STRIDE;
        if (st < 10) {
            unsigned anb = abase + (unsigned)(((st + 1) & 1) * 128 * XA_STRIDE) * 4;
            int kb = (st + 1) * 24;
            for (int q = tid; q < 128 * 6; q += 256) {
                int r = q / 6, c = q - r * 6;
                cpa16(anb + (unsigned)(r * XA_STRIDE + c * 4) * 4,
                      d_xt + (row0 + r) * KP + kb + c * 4);
            }
            cp_commit();
            cp_wait1();
        } else {
            cp_wait0();
        }
        __syncthreads();
#pragma unroll
        for (int k8 = 0; k8 < 3; k8++) {
            int kk = k8 * 8;
            unsigned afr[2][4];
#pragma unroll
            for (int mt = 0; mt < 2; mt++) {
                const float* p = Ab + (wm * 32 + mt * 16 + lr) * XA_STRIDE + kk + lc;
                afr[mt][0] = __float_as_uint(p[0]);
                afr[mt][1] = __float_as_uint(p[8 * XA_STRIDE]);
                afr[mt][2] = __float_as_uint(p[4]);
                afr[mt][3] = __float_as_uint(p[8 * XA_STRIDE + 4]);
            }
#pragma unroll
            for (int nt = 0; nt < 4; nt++) {
                const float* p = Wsm + (wn * 32 + nt * 8 + lr) * XW_STRIDE + st * 24 + kk + lc;
                unsigned bfr[2] = { __float_as_uint(p[0]), __float_as_uint(p[4]) };
#pragma unroll
                for (int mt = 0; mt < 2; mt++) mma8(acc[mt][nt], afr[mt], bfr);
            }
        }
        __syncthreads();
    }

    // epilogue: add bias, store to d_xg
#pragma unroll
    for (int mt = 0; mt < 2; mt++) {
#pragma unroll
        for (int nt = 0; nt < 4; nt++) {
            int g = n0 + wn * 32 + nt * 8 + 2 * lc;
            float2 bias = *(const float2*)(d_bias + g);
#pragma unroll
            for (int p = 0; p < 2; p++) {
                int row = row0 + wm * 32 + mt * 16 + lr + p * 8;
                float2 o;
                o.x = acc[mt][nt][2 * p + 0] + bias.x;
                o.y = acc[mt][nt][2 * p + 1] + bias.y;
                *(float2*)(d_xg + (size_t)row * NG + g) = o;
            }
        }
    }
}

// ---------------- persistent recurrent kernel ----------------
// 128 CTAs; CTA cid owns hidden units [8*cid, 8*cid+8) = 32 gate columns.
// W_hh slice resident in smem for all 512 steps; h streamed via cp.async.cg.
#define RW_STRIDE 1028
#define RA_STRIDE 36
#define R_SMEM (32 * RW_STRIDE * 4 + 2 * 128 * RA_STRIDE * 4 + 1024 * 4)

__global__ void __launch_bounds__(256, 1) k_rec() {
    extern __shared__ float sm[];
    float* Wsm = sm;                                 // [32][1028]
    float* Asm = sm + 32 * RW_STRIDE;                // [2][128][36]
    float* Csm = Asm + 2 * 128 * RA_STRIDE;          // [1024] cell state slice
    float* Gsm = Asm;                                // reuse A-buf0 [128][36] for gate staging

    const int tid = threadIdx.x;
    const int cid = blockIdx.x;                      // 0..127
    const int J0 = cid * 8;
    unsigned wbase = smem_u32(Wsm);
    unsigned abase = smem_u32(Asm);

    // load W rows: local row r -> gate (r>>3), hidden J0+(r&7)
    for (int q = tid; q < 32 * 256; q += 256) {
        int r = q >> 8, c = q & 255;
        int gcol = ((r >> 3) << 10) + J0 + (r & 7);
        cpa16(wbase + (unsigned)(r * RW_STRIDE + c * 4) * 4, d_whh + (size_t)gcol * NH + c * 4);
    }
    cp_commit();

    // zero our h slice (buffer 0) and cell state
    for (int u = tid; u < 1024; u += 256) {
        d_h[0][(u >> 3) * NH + J0 + (u & 7)] = 0.f;
        Csm[u] = 0.f;
    }
    cp_wait0();
    __syncthreads();
    gbar(128ULL);   // all h zeroed, all W resident

    const int wid = tid >> 5, l = tid & 31;
    const int wm = wid >> 1, wn = wid & 1;           // 4 x 2 warps, warp tile 32x16
    const int lr = l >> 2, lc = l & 3;

    for (int s = 0; s < NS; s++) {
        const float* hr = d_h[s & 1];
        float* hw = d_h[(s + 1) & 1];
        const float* xgS = d_xg + (size_t)s * NB * NG;

        float acc[2][2][4];
#pragma unroll
        for (int i = 0; i < 2; i++)
#pragma unroll
            for (int j = 0; j < 2; j++)
#pragma unroll
                for (int k = 0; k < 4; k++) acc[i][j][k] = 0.f;

        // prefetch stage 0 of h (128 x 32 floats)
        for (int q = tid; q < 128 * 8; q += 256) {
            int r = q >> 3, c = q & 7;
            cpa16(abase + (unsigned)(r * RA_STRIDE + c * 4) * 4, hr + r * NH + c * 4);
        }
        cp_commit();

        for (int st = 0; st < 32; st++) {
            float* Ab = Asm + (st & 1) * 128 * RA_STRIDE;
            if (st < 31) {
                unsigned anb = abase + (unsigned)(((st + 1) & 1) * 128 * RA_STRIDE) * 4;
                int kb = (st + 1) * 32;
                for (int q = tid; q < 128 * 8; q += 256) {
                    int r = q >> 3, c = q & 7;
                    cpa16(anb + (unsigned)(r * RA_STRIDE + c * 4) * 4, hr + r * NH + kb + c * 4);
                }
                cp_commit();
                cp_wait1();
            } else {
                cp_wait0();
            }
            __syncthreads();
#pragma unroll
            for (int k8 = 0; k8 < 4; k8++) {
                int kk = k8 * 8;
                unsigned afr[2][4];
#pragma unroll
                for (int mt = 0; mt < 2; mt++) {
                    const float* p = Ab + (wm * 32 + mt * 16 + lr) * RA_STRIDE + kk + lc;
                    afr[mt][0] = __float_as_uint(p[0]);
                    afr[mt][1] = __float_as_uint(p[8 * RA_STRIDE]);
                    afr[mt][2] = __float_as_uint(p[4]);
                    afr[mt][3] = __float_as_uint(p[8 * RA_STRIDE + 4]);
                }
#pragma unroll
                for (int nt = 0; nt < 2; nt++) {
                    const float* p = Wsm + (wn * 16 + nt * 8 + lr) * RW_STRIDE + st * 32 + kk + lc;
                    unsigned bfr[2] = { __float_as_uint(p[0]), __float_as_uint(p[4]) };
#pragma unroll
                    for (int mt = 0; mt < 2; mt++) mma8(acc[mt][nt], afr[mt], bfr);
                }
            }
            __syncthreads();
        }

        // epilogue: G = acc + xg -> smem (last compute stage used A-buf1; buf0 free)
#pragma unroll
        for (int mt = 0; mt < 2; mt++) {
#pragma unroll
            for (int nt = 0; nt < 2; nt++) {
                int lcol = wn * 16 + nt * 8 + 2 * lc;                  // 0..31
                int gcol = ((lcol >> 3) << 10) + J0 + (lcol & 7);
#pragma unroll
                for (int p = 0; p < 2; p++) {
                    int m = wm * 32 + mt * 16 + lr + p * 8;
                    float2 xv = *(const float2*)(xgS + (size_t)m * NG + gcol);
                    float2 o;
                    o.x = acc[mt][nt][2 * p + 0] + xv.x;
                    o.y = acc[mt][nt][2 * p + 1] + xv.y;
                    *(float2*)(Gsm + m * RA_STRIDE + lcol) = o;
                }
            }
        }
        __syncthreads();

        // elementwise LSTM cell for our 8 hidden units x 128 batches
#pragma unroll
        for (int q = 0; q < 4; q++) {
            int u = tid + q * 256;
            int m = u >> 3, jj = u & 7;
            const float* Gr = Gsm + m * RA_STRIDE;
            float iv = sigf(Gr[jj]);
            float fv = sigf(Gr[8 + jj]);
            float gv = tanhf_(Gr[16 + jj]);
            float ov = sigf(Gr[24 + jj]);
            float cv = fv * Csm[u] + iv * gv;
            Csm[u] = cv;
            float hv = ov * tanhf_(cv);
            hw[m * NH + J0 + jj] = to_tf32(hv);
        }
        gbar(128ULL * (unsigned long long)(s + 2));
    }
}

// ---------------- final FC: out = h_last @ W_fc.T + b_fc ----------------
__global__ void k_fc(const float* __restrict__ wfc, const float* __restrict__ bfc,
                     float* __restrict__ out) {
    int idx = blockIdx.x * 256 + threadIdx.x;
    if (idx >= NB * NO) return;
    int b = idx >> 6, o = idx & 63;
    const float4* h = (const float4*)(d_h[0] + b * NH);   // NS even -> final h in buffer 0
    const float4* w = (const float4*)(wfc + o * NH);
    float sacc = 0.f;
#pragma unroll 8
    for (int k = 0; k < NH / 4; k++) {
        float4 hv = h[k], wv = w[k];
        sacc += hv.x * wv.x + hv.y * wv.y + hv.z * wv.z + hv.w * wv.w;
    }
    out[idx] = sacc + bfc[o];
}

// ---------------- launch ----------------
extern "C" void kernel_launch(void* const* d_in, const int* in_sizes, int n_in,
                              void* d_out, int out_size) {
    const float* x    = (const float*)d_in[0];
    const float* mask = (const float*)d_in[1];
    const float* ti   = (const float*)d_in[2];
    const float* wih  = (const float*)d_in[3];
    const float* whh  = (const float*)d_in[4];
    const float* bih  = (const float*)d_in[5];
    const float* bhh  = (const float*)d_in[6];
    const float* wfc  = (const float*)d_in[7];
    const float* bfc  = (const float*)d_in[8];
    float* out = (float*)d_out;

    cudaFuncSetAttribute(k_xg, cudaFuncAttributeMaxDynamicSharedMemorySize, XG_SMEM);
    cudaFuncSetAttribute(k_rec, cudaFuncAttributeMaxDynamicSharedMemorySize, R_SMEM);

    k_prep_xt<<<(NS * NB * KP + 255) / 256, 256>>>(x, mask, ti);
    k_prep_w<<<(NG * NH + 255) / 256, 256>>>(wih, whh, bih, bhh);
    k_xg<<<dim3(64, 512), 256, XG_SMEM>>>();
    k_rec<<<128, 256, R_SMEM>>>();
    k_fc<<<(NB * NO + 255) / 256, 256>>>(wfc, bfc, out);
}